// round 4
// baseline (speedup 1.0000x reference)
#include <cuda_runtime.h>
#include <math.h>

#define TPB   768
#define BM    4
#define S_LEN 128
#define B_TOT 512
#define H     192
#define VOC   256
#define PP    64
#define PHH   16

// output buffer offsets (floats), concatenated in reference-return order
#define OFF_LOGITS 0
#define OFF_HIDDEN (512*128*256)
#define OFF_PW     (OFF_HIDDEN + 512*128*192)
#define OFF_PHW    (OFF_PW     + 512*128*64)
#define OFF_GATE   (OFF_PHW    + 512*128*16)

typedef unsigned long long u64t;

__device__ __forceinline__ u64t ffma2(u64t a, u64t b, u64t c) {
    u64t d;
    asm("fma.rn.f32x2 %0, %1, %2, %3;" : "=l"(d) : "l"(a), "l"(b), "l"(c));
    return d;
}

__device__ __forceinline__ float geluf(float x) {
    return 0.5f * x * (1.0f + erff(x * 0.7071067811865475f));
}

struct __align__(16) Smem {
    float xbuf[BM * 576 * 2];   // dup-format concat GEMM input (rows: 2K floats)
    float red [12288];          // k-split partial scratch: NSEG*BM*N == 12288 for all shapes
    float tok [BM * H];
    float prev[BM * H];
    float patch[BM * H];
    float sec [BM * H];
    float phs [BM * H];
    float succ[BM * H];
    float hbuf[BM * H];         // normal-format (gate1 out)
    float hbufd[BM * H * 2];    // dup-format (bind1/succ1 out)
    float z64 [BM * PP];
    float z64d[BM * PP * 2];
    float z16 [BM * PHH];
    float z16d[BM * PHH * 2];
    float gate[BM];
    int   ids [BM];
};

// C[BM x N] = act( X[BM x K] @ W[K x N] + bias )
// X is in DUP format: row r is K u64 entries, entry k = {x_k, x_k} packed f32x2.
// thread -> (col-pair group c4 = t % (N/4) owning 4 cols, kseg = t / (N/4)).
// ACT: 0 = none, 1 = gelu(exact), 2 = tanh. OUTDUP: write outs in dup format.
template<int K, int N, int ACT, bool HASB, bool OUTDUP>
__device__ __forceinline__ void gemm(const float* __restrict__ xd,
                                     const float* __restrict__ W,
                                     const float* __restrict__ bias,
                                     float* __restrict__ red,
                                     float* __restrict__ outs,
                                     float* __restrict__ outg, int g_rstride)
{
    constexpr int NC4  = N / 4;
    constexpr int NSEG = TPB / NC4;
    constexpr int KS   = K / NSEG;
    static_assert(NC4 * NSEG == TPB, "thread mapping must be exact");
    static_assert(KS * NSEG == K,    "k split must be exact");

    const int t   = threadIdx.x;
    const int c4  = t % NC4;
    const int seg = t / NC4;
    const ulonglong2* __restrict__ Wu = reinterpret_cast<const ulonglong2*>(W);

    ulonglong2 acc2[BM];
#pragma unroll
    for (int r = 0; r < BM; r++) { acc2[r].x = 0ull; acc2[r].y = 0ull; }

    const int k0 = seg * KS;

    if constexpr ((KS % 4) == 0) {
        const ulonglong2* __restrict__ Xu2 = reinterpret_cast<const ulonglong2*>(xd);
#pragma unroll 2
        for (int kk4 = 0; kk4 < KS / 4; kk4++) {
            const int k = k0 + kk4 * 4;
            ulonglong2 u[BM];
#pragma unroll
            for (int r = 0; r < BM; r++) u[r] = Xu2[(r * K + k) >> 1];
            ulonglong2 w0 = __ldg(&Wu[(k + 0) * NC4 + c4]);
            ulonglong2 w1 = __ldg(&Wu[(k + 1) * NC4 + c4]);
#pragma unroll
            for (int r = 0; r < BM; r++) {
                acc2[r].x = ffma2(u[r].x, w0.x, acc2[r].x);
                acc2[r].y = ffma2(u[r].x, w0.y, acc2[r].y);
                acc2[r].x = ffma2(u[r].y, w1.x, acc2[r].x);
                acc2[r].y = ffma2(u[r].y, w1.y, acc2[r].y);
            }
#pragma unroll
            for (int r = 0; r < BM; r++) u[r] = Xu2[((r * K + k) >> 1) + 1];
            ulonglong2 w2 = __ldg(&Wu[(k + 2) * NC4 + c4]);
            ulonglong2 w3 = __ldg(&Wu[(k + 3) * NC4 + c4]);
#pragma unroll
            for (int r = 0; r < BM; r++) {
                acc2[r].x = ffma2(u[r].x, w2.x, acc2[r].x);
                acc2[r].y = ffma2(u[r].x, w2.y, acc2[r].y);
                acc2[r].x = ffma2(u[r].y, w3.x, acc2[r].x);
                acc2[r].y = ffma2(u[r].y, w3.y, acc2[r].y);
            }
        }
    } else {
        const u64t* __restrict__ Xu = reinterpret_cast<const u64t*>(xd);
#pragma unroll
        for (int kk = 0; kk < KS; kk++) {
            const int k = k0 + kk;
            ulonglong2 w = __ldg(&Wu[k * NC4 + c4]);
#pragma unroll
            for (int r = 0; r < BM; r++) {
                u64t xx = Xu[r * K + k];
                acc2[r].x = ffma2(xx, w.x, acc2[r].x);
                acc2[r].y = ffma2(xx, w.y, acc2[r].y);
            }
        }
    }

    ulonglong2* redv = reinterpret_cast<ulonglong2*>(red);
#pragma unroll
    for (int r = 0; r < BM; r++) redv[(seg * BM + r) * NC4 + c4] = acc2[r];
    __syncthreads();

    for (int i = t; i < BM * N; i += TPB) {
        const int r = i / N;
        const int n = i % N;
        float v = 0.f;
#pragma unroll
        for (int g = 0; g < NSEG; g++) v += red[(g * BM + r) * N + n];
        if (HASB) v += __ldg(&bias[n]);
        if (ACT == 1) v = geluf(v);
        if (ACT == 2) v = tanhf(v);
        if (outs) {
            if (OUTDUP) {
                float2 d2 = make_float2(v, v);
                *reinterpret_cast<float2*>(&outs[(r * N + n) * 2]) = d2;
            } else {
                outs[i] = v;
            }
        }
        if (outg) outg[r * g_rstride + n] = v;
    }
    __syncthreads();
}

// warp-per-row softmax over N (<= 64): reads z (normal), writes zd (dup) + global
template<int N>
__device__ __forceinline__ void softmax_rows(const float* __restrict__ z,
                                             float* __restrict__ zd,
                                             float* __restrict__ outg, int g_rstride)
{
    const int w = threadIdx.x >> 5, lane = threadIdx.x & 31;
    if (w < BM) {
        const float* row = z + w * N;
        constexpr int PER = (N + 31) / 32;
        float m = -3.0e38f;
#pragma unroll
        for (int i = 0; i < PER; i++) {
            int n = lane + 32 * i;
            if (n < N) m = fmaxf(m, row[n]);
        }
#pragma unroll
        for (int o = 16; o; o >>= 1) m = fmaxf(m, __shfl_xor_sync(0xffffffffu, m, o));
        float ev[PER];
        float sum = 0.f;
#pragma unroll
        for (int i = 0; i < PER; i++) {
            int n = lane + 32 * i;
            if (n < N) { ev[i] = expf(row[n] - m); sum += ev[i]; }
        }
#pragma unroll
        for (int o = 16; o; o >>= 1) sum += __shfl_xor_sync(0xffffffffu, sum, o);
        const float inv = 1.f / sum;
#pragma unroll
        for (int i = 0; i < PER; i++) {
            int n = lane + 32 * i;
            if (n < N) {
                float v = ev[i] * inv;
                *reinterpret_cast<float2*>(&zd[(w * N + n) * 2]) = make_float2(v, v);
                outg[w * g_rstride + n] = v;
            }
        }
    }
}

__global__ void __launch_bounds__(TPB, 1)
spike_kernel(const int* __restrict__ ids_g,      const float* __restrict__ emb,
             const float* __restrict__ sel_W,    const float* __restrict__ sel_b,
             const float* __restrict__ patch_values,
             const float* __restrict__ bind_W1,  const float* __restrict__ bind_b1,
             const float* __restrict__ bind_W2,  const float* __restrict__ bind_b2,
             const float* __restrict__ phase_embed,
             const float* __restrict__ router_W, const float* __restrict__ router_b,
             const float* __restrict__ succ_W1,  const float* __restrict__ succ_b1,
             const float* __restrict__ succ_W2,  const float* __restrict__ succ_b2,
             const float* __restrict__ gate_W1,  const float* __restrict__ gate_b1,
             const float* __restrict__ gate_W2,  const float* __restrict__ gate_b2,
             const float* __restrict__ ln_g,     const float* __restrict__ ln_b,
             const float* __restrict__ dec_W,
             float* __restrict__ out)
{
    __shared__ Smem sm;
    const int t  = threadIdx.x;
    const int b0 = blockIdx.x * BM;

    float* out_logits = out + OFF_LOGITS;
    float* out_hidden = out + OFF_HIDDEN;
    float* out_pw     = out + OFF_PW;
    float* out_phw    = out + OFF_PHW;
    float* out_gate   = out + OFF_GATE;

    for (int i = t; i < BM * H; i += TPB) sm.prev[i] = 0.f;
    __syncthreads();

    for (int s = 0; s < S_LEN; s++) {
        if (t < BM) sm.ids[t] = ids_g[(b0 + t) * S_LEN + s];
        __syncthreads();

        // tok gather + build x1 = dup[tok, prev] (K=384)
        for (int i = t; i < BM * 384; i += TPB) {
            const int r = i / 384, k = i % 384;
            float v;
            if (k < H) { v = __ldg(&emb[sm.ids[r] * H + k]); sm.tok[r * H + k] = v; }
            else       { v = sm.prev[r * H + (k - H)]; }
            *reinterpret_cast<float2*>(&sm.xbuf[(r * 384 + k) * 2]) = make_float2(v, v);
        }
        __syncthreads();

        // patch selector: softmax(x1 @ sel_W + b) @ patch_values
        gemm<384, PP, 0, true, false>(sm.xbuf, sel_W, sel_b, sm.red, sm.z64, nullptr, 0);
        softmax_rows<PP>(sm.z64, sm.z64d, out_pw + (b0 * S_LEN + s) * PP, S_LEN * PP);
        __syncthreads();
        gemm<PP, H, 0, false, false>(sm.z64d, patch_values, nullptr, sm.red, sm.patch, nullptr, 0);

        // section binder: tanh(gelu(dup[tok,patch,prev] @ W1 + b1) @ W2 + b2)
        for (int i = t; i < BM * 576; i += TPB) {
            const int r = i / 576, k = i % 576;
            float v = (k < H) ? sm.tok[r * H + k]
                    : (k < 2 * H) ? sm.patch[r * H + (k - H)]
                                  : sm.prev[r * H + (k - 2 * H)];
            *reinterpret_cast<float2*>(&sm.xbuf[i * 2]) = make_float2(v, v);
        }
        __syncthreads();
        gemm<576, H, 1, true, true >(sm.xbuf,  bind_W1, bind_b1, sm.red, sm.hbufd, nullptr, 0);
        gemm<H,   H, 2, true, false>(sm.hbufd, bind_W2, bind_b2, sm.red, sm.sec,   nullptr, 0);

        // phase routing: softmax(dup[sec,prev] @ router_W + b) @ phase_embed
        for (int i = t; i < BM * 384; i += TPB) {
            const int r = i / 384, k = i % 384;
            float v = (k < H) ? sm.sec[r * H + k] : sm.prev[r * H + (k - H)];
            *reinterpret_cast<float2*>(&sm.xbuf[(r * 384 + k) * 2]) = make_float2(v, v);
        }
        __syncthreads();
        gemm<384, PHH, 0, true, false>(sm.xbuf, router_W, router_b, sm.red, sm.z16, nullptr, 0);
        softmax_rows<PHH>(sm.z16, sm.z16d, out_phw + (b0 * S_LEN + s) * PHH, S_LEN * PHH);
        __syncthreads();
        gemm<PHH, H, 0, false, false>(sm.z16d, phase_embed, nullptr, sm.red, sm.phs, nullptr, 0);

        // successor: tanh(gelu(dup[sec,patch,phs] @ W1 + b1) @ W2 + b2)
        for (int i = t; i < BM * 576; i += TPB) {
            const int r = i / 576, k = i % 576;
            float v = (k < H) ? sm.sec[r * H + k]
                    : (k < 2 * H) ? sm.patch[r * H + (k - H)]
                                  : sm.phs[r * H + (k - 2 * H)];
            *reinterpret_cast<float2*>(&sm.xbuf[i * 2]) = make_float2(v, v);
        }
        __syncthreads();
        gemm<576, H, 1, true, true >(sm.xbuf,  succ_W1, succ_b1, sm.red, sm.hbufd, nullptr, 0);
        gemm<H,   H, 2, true, false>(sm.hbufd, succ_W2, succ_b2, sm.red, sm.succ,  nullptr, 0);

        // gate: sigmoid(gelu(dup[succ,prev] @ gW1 + b1) @ gW2 + b2)
        for (int i = t; i < BM * 384; i += TPB) {
            const int r = i / 384, k = i % 384;
            float v = (k < H) ? sm.succ[r * H + k] : sm.prev[r * H + (k - H)];
            *reinterpret_cast<float2*>(&sm.xbuf[(r * 384 + k) * 2]) = make_float2(v, v);
        }
        __syncthreads();
        gemm<384, H, 1, true, false>(sm.xbuf, gate_W1, gate_b1, sm.red, sm.hbuf, nullptr, 0);
        {
            const int w = t >> 5, lane = t & 31;
            if (w < BM) {
                float v = 0.f;
#pragma unroll
                for (int i = 0; i < H / 32; i++) {
                    const int k = lane + 32 * i;
                    v = fmaf(sm.hbuf[w * H + k], __ldg(&gate_W2[k]), v);
                }
#pragma unroll
                for (int o = 16; o; o >>= 1) v += __shfl_xor_sync(0xffffffffu, v, o);
                v += gate_b2[0];
                const float gt = 1.f / (1.f + expf(-v));
                if (lane == 0) {
                    sm.gate[w] = gt;
                    out_gate[(b0 + w) * S_LEN + s] = gt;
                }
            }
        }
        __syncthreads();

        // hidden = gate*succ + (1-gate)*prev ; layernorm ; becomes prev (+dup into xbuf for dec)
        {
            const int w = t >> 5, lane = t & 31;
            if (w < BM) {
                const float g = sm.gate[w];
                float lv[H / 32];
                float mean = 0.f;
#pragma unroll
                for (int i = 0; i < H / 32; i++) {
                    const int h = lane + 32 * i;
                    float hv = g * sm.succ[w * H + h] + (1.f - g) * sm.prev[w * H + h];
                    lv[i] = hv; mean += hv;
                }
#pragma unroll
                for (int o = 16; o; o >>= 1) mean += __shfl_xor_sync(0xffffffffu, mean, o);
                mean *= (1.f / (float)H);
                float var = 0.f;
#pragma unroll
                for (int i = 0; i < H / 32; i++) { float d = lv[i] - mean; var = fmaf(d, d, var); }
#pragma unroll
                for (int o = 16; o; o >>= 1) var += __shfl_xor_sync(0xffffffffu, var, o);
                var *= (1.f / (float)H);
                const float rstd = rsqrtf(var + 1e-5f);
                float* oh = out_hidden + ((b0 + w) * S_LEN + s) * H;
#pragma unroll
                for (int i = 0; i < H / 32; i++) {
                    const int h = lane + 32 * i;
                    float o = (lv[i] - mean) * rstd * ln_g[h] + ln_b[h];
                    sm.prev[w * H + h] = o;
                    *reinterpret_cast<float2*>(&sm.xbuf[(w * H + h) * 2]) = make_float2(o, o);
                    oh[h] = o;
                }
            }
        }
        __syncthreads();

        // readout: logits = hidden @ dec_W
        gemm<H, VOC, 0, false, false>(sm.xbuf, dec_W, nullptr, sm.red, nullptr,
                                      out_logits + (b0 * S_LEN + s) * VOC, S_LEN * VOC);
    }
}

extern "C" void kernel_launch(void* const* d_in, const int* in_sizes, int n_in,
                              void* d_out, int out_size)
{
    const int*   ids          = (const int*)  d_in[0];
    const float* emb          = (const float*)d_in[1];
    const float* sel_W        = (const float*)d_in[2];
    const float* sel_b        = (const float*)d_in[3];
    const float* patch_values = (const float*)d_in[4];
    const float* bind_W1      = (const float*)d_in[5];
    const float* bind_b1      = (const float*)d_in[6];
    const float* bind_W2      = (const float*)d_in[7];
    const float* bind_b2      = (const float*)d_in[8];
    const float* phase_embed  = (const float*)d_in[9];
    const float* router_W     = (const float*)d_in[10];
    const float* router_b     = (const float*)d_in[11];
    const float* succ_W1      = (const float*)d_in[12];
    const float* succ_b1      = (const float*)d_in[13];
    const float* succ_W2      = (const float*)d_in[14];
    const float* succ_b2      = (const float*)d_in[15];
    const float* gate_W1      = (const float*)d_in[16];
    const float* gate_b1      = (const float*)d_in[17];
    const float* gate_W2      = (const float*)d_in[18];
    const float* gate_b2      = (const float*)d_in[19];
    const float* ln_g         = (const float*)d_in[20];
    const float* ln_b         = (const float*)d_in[21];
    const float* dec_W        = (const float*)d_in[22];

    spike_kernel<<<B_TOT / BM, TPB>>>(
        ids, emb, sel_W, sel_b, patch_values,
        bind_W1, bind_b1, bind_W2, bind_b2,
        phase_embed, router_W, router_b,
        succ_W1, succ_b1, succ_W2, succ_b2,
        gate_W1, gate_b1, gate_W2, gate_b2,
        ln_g, ln_b, dec_W, (float*)d_out);
}